// round 1
// baseline (speedup 1.0000x reference)
#include <cuda_runtime.h>
#include <cuda_bf16.h>
#include <math.h>

// ---------------- problem constants ----------------
#define BB 2
#define TT 1024
#define CC 1024
#define HH 16
#define HD 64
#define LL 6
#define PP 4
#define VV 32000
#define MTOK (BB*TT)          // 2048 rows

// ---------------- scratch (no allocation allowed) ----------------
__device__ float g_x   [MTOK * CC];        // residual stream
__device__ float g_h   [MTOK * CC];        // rmsnorm output
__device__ float g_qkv [MTOK * 3 * CC];    // qkv
__device__ float g_attn[MTOK * CC];        // attention output
__device__ float g_ff  [MTOK * PP * CC];   // ff hidden

// ---------------- embedding gather ----------------
__global__ void embed_kernel(const int* __restrict__ tokens,
                             const float* __restrict__ table,
                             float* __restrict__ x)
{
    int row = blockIdx.x;                      // 0..2047
    int tok = tokens[row];
    const float4* src = (const float4*)(table + (size_t)tok * CC);
    float4* dst = (float4*)(x + (size_t)row * CC);
    dst[threadIdx.x] = src[threadIdx.x];       // 256 threads x float4 = 1024 floats
}

// ---------------- rmsnorm ----------------
__global__ void rmsnorm_kernel(const float* __restrict__ x,
                               const float* __restrict__ g,
                               float* __restrict__ h)
{
    int row = blockIdx.x;
    int tid = threadIdx.x;
    const float* xr = x + (size_t)row * CC;
    float ss = 0.f;
    #pragma unroll
    for (int i = tid; i < CC; i += 256) { float v = xr[i]; ss += v * v; }
    // block reduce
    for (int o = 16; o > 0; o >>= 1) ss += __shfl_down_sync(0xffffffffu, ss, o);
    __shared__ float warp_s[8];
    __shared__ float sscale;
    int lane = tid & 31, wid = tid >> 5;
    if (lane == 0) warp_s[wid] = ss;
    __syncthreads();
    if (tid == 0) {
        float tot = 0.f;
        #pragma unroll
        for (int i = 0; i < 8; i++) tot += warp_s[i];
        sscale = rsqrtf(tot / (float)CC + 1.1920929e-07f);
    }
    __syncthreads();
    float s = sscale;
    float* hr = h + (size_t)row * CC;
    #pragma unroll
    for (int i = tid; i < CC; i += 256) hr[i] = xr[i] * s * g[i];
}

// ---------------- RoPE on q,k thirds of qkv ----------------
// pairs over full C: pair i in [0,512), cols (2i, 2i+1); theta_i = 10000^(-i/512)
__global__ void rope_kernel(float* __restrict__ qkv)
{
    int row = blockIdx.x;              // 0..2047
    int t = row & (TT - 1);
    int p = blockIdx.y * 128 + threadIdx.x;   // 0..1023
    int region = (p < 512) ? 0 : 1;           // 0 = q, 1 = k
    int i = p - region * 512;
    double theta = exp(-(double)i * (9.210340371976184 / 512.0));
    double ang = (double)t * theta;
    float c = (float)cos(ang);
    float s = (float)sin(ang);
    float* base = qkv + (size_t)row * (3 * CC) + region * CC + 2 * i;
    float x0 = base[0], x1 = base[1];
    base[0] = x0 * c - x1 * s;
    base[1] = x1 * c + x0 * s;
}

// ---------------- flash-style attention (fp32) ----------------
// grid (T/64, H, B), 64 threads. Thread owns one query row.
// K tile = 32 keys.
__global__ void attention_kernel(const float* __restrict__ qkv,
                                 float* __restrict__ out)
{
    __shared__ float Ks[32][64];
    __shared__ float Vs[32][64];
    __shared__ float Ps[32][64];   // [kk][tid] -> conflict-free
    int mt = blockIdx.x, h = blockIdx.y, b = blockIdx.z;
    int tid = threadIdx.x;
    int qrow = mt * 64 + tid;

    const float* qp = qkv + ((size_t)(b * TT + qrow) * (3 * CC)) + h * HD;
    float q[64];
    #pragma unroll
    for (int u = 0; u < 16; u++) {
        float4 v = *(const float4*)(qp + 4 * u);
        q[4*u+0] = v.x; q[4*u+1] = v.y; q[4*u+2] = v.z; q[4*u+3] = v.w;
    }
    float acc[64];
    #pragma unroll
    for (int u = 0; u < 64; u++) acc[u] = 0.f;
    float mrun = -1e30f, lsum = 0.f;

    int jmax = 2 * mt + 1;   // last 32-key tile needed by this query block
    int krow = tid >> 1;
    int seg  = (tid & 1) * 32;
    for (int j = 0; j <= jmax; j++) {
        // cooperative load of K/V tile (keys j*32 .. j*32+31)
        const float* kp = qkv + ((size_t)(b * TT + j * 32 + krow) * (3 * CC)) + CC + h * HD + seg;
        const float* vp = kp + CC;
        #pragma unroll
        for (int u = 0; u < 8; u++) {
            *(float4*)&Ks[krow][seg + 4*u] = *(const float4*)(kp + 4*u);
            *(float4*)&Vs[krow][seg + 4*u] = *(const float4*)(vp + 4*u);
        }
        __syncthreads();

        float tmax = -1e30f;
        #pragma unroll 4
        for (int kk = 0; kk < 32; kk++) {
            int kt = j * 32 + kk;
            float s = -1e30f;
            if (kt <= qrow) {
                float d = 0.f;
                #pragma unroll
                for (int u = 0; u < 64; u++) d += q[u] * Ks[kk][u];
                s = d * 0.125f;
            }
            Ps[kk][tid] = s;
            tmax = fmaxf(tmax, s);
        }
        float mnew = fmaxf(mrun, tmax);
        float corr = expf(mrun - mnew);
        lsum *= corr;
        #pragma unroll
        for (int u = 0; u < 64; u++) acc[u] *= corr;
        #pragma unroll 2
        for (int kk = 0; kk < 32; kk++) {
            float p = expf(Ps[kk][tid] - mnew);
            lsum += p;
            #pragma unroll
            for (int u = 0; u < 64; u++) acc[u] += p * Vs[kk][u];
        }
        mrun = mnew;
        __syncthreads();
    }
    float inv = 1.0f / lsum;
    float* op = out + ((size_t)(b * TT + qrow) * CC) + h * HD;
    #pragma unroll
    for (int u = 0; u < 64; u++) op[u] = acc[u] * inv;
}

// ---------------- SGEMM 128x128x8, 256 threads, 8x8 per thread ----------------
// C[M,N] = A[M,K] @ B[K,N] (+bias) (+gelu | +residual)
// mode: 0 = bias, 1 = bias+gelu, 2 = bias+residual(res)
__global__ __launch_bounds__(256, 2)
void sgemm_kernel(const float* __restrict__ A, const float* __restrict__ B,
                  const float* __restrict__ bias, const float* __restrict__ res,
                  float* __restrict__ C, int M, int N, int K, int mode)
{
    __shared__ float As[8][128];
    __shared__ float Bs[8][128];
    int tid = threadIdx.x;
    int bm = blockIdx.y * 128;
    int bn = blockIdx.x * 128;

    int arow  = tid >> 1;          // 0..127
    int acol4 = (tid & 1) * 4;     // 0 or 4
    int brow  = tid >> 5;          // 0..7
    int bcol4 = (tid & 31) * 4;    // 0..124
    int tx = (tid & 15) * 8;       // col offset in tile
    int ty = (tid >> 4) * 8;       // row offset in tile

    const float* Aptr = A + (size_t)(bm + arow) * K + acol4;
    const float* Bptr = B + (size_t)brow * N + bn + bcol4;

    float acc[8][8];
    #pragma unroll
    for (int i = 0; i < 8; i++)
        #pragma unroll
        for (int j = 0; j < 8; j++) acc[i][j] = 0.f;

    for (int k0 = 0; k0 < K; k0 += 8) {
        float4 av = *(const float4*)Aptr;
        As[acol4+0][arow] = av.x;
        As[acol4+1][arow] = av.y;
        As[acol4+2][arow] = av.z;
        As[acol4+3][arow] = av.w;
        *(float4*)&Bs[brow][bcol4] = *(const float4*)Bptr;
        __syncthreads();
        #pragma unroll
        for (int k = 0; k < 8; k++) {
            float a[8], bfr[8];
            float4 a0 = *(float4*)&As[k][ty];
            float4 a1 = *(float4*)&As[k][ty+4];
            a[0]=a0.x; a[1]=a0.y; a[2]=a0.z; a[3]=a0.w;
            a[4]=a1.x; a[5]=a1.y; a[6]=a1.z; a[7]=a1.w;
            float4 b0 = *(float4*)&Bs[k][tx];
            float4 b1 = *(float4*)&Bs[k][tx+4];
            bfr[0]=b0.x; bfr[1]=b0.y; bfr[2]=b0.z; bfr[3]=b0.w;
            bfr[4]=b1.x; bfr[5]=b1.y; bfr[6]=b1.z; bfr[7]=b1.w;
            #pragma unroll
            for (int i = 0; i < 8; i++)
                #pragma unroll
                for (int j = 0; j < 8; j++)
                    acc[i][j] += a[i] * bfr[j];
        }
        __syncthreads();
        Aptr += 8;
        Bptr += (size_t)8 * N;
    }

    // epilogue
    #pragma unroll
    for (int i = 0; i < 8; i++) {
        int row = bm + ty + i;
        #pragma unroll
        for (int j = 0; j < 8; j++) {
            int col = bn + tx + j;
            float v = acc[i][j];
            if (bias) v += bias[col];
            if (mode == 1) {
                v = 0.5f * v * (1.0f + erff(v * 0.7071067811865475f));
            } else if (mode == 2) {
                v += res[(size_t)row * N + col];
            }
            C[(size_t)row * N + col] = v;
        }
    }
}

// ---------------- launch ----------------
extern "C" void kernel_launch(void* const* d_in, const int* in_sizes, int n_in,
                              void* d_out, int out_size)
{
    const int*   tokens      = (const int*)  d_in[0];
    const float* embed_table = (const float*)d_in[1];
    const float* w_attn      = (const float*)d_in[2];
    const float* b_attn      = (const float*)d_in[3];
    const float* w_proj      = (const float*)d_in[4];
    const float* b_proj      = (const float*)d_in[5];
    const float* g1          = (const float*)d_in[6];
    const float* g2          = (const float*)d_in[7];
    const float* w_ff1       = (const float*)d_in[8];
    const float* b_ff1       = (const float*)d_in[9];
    const float* w_ff2       = (const float*)d_in[10];
    const float* b_ff2       = (const float*)d_in[11];
    const float* w_out       = (const float*)d_in[12];
    float* out = (float*)d_out;

    float *x, *h, *qkv, *attn, *ff;
    cudaGetSymbolAddress((void**)&x,    g_x);
    cudaGetSymbolAddress((void**)&h,    g_h);
    cudaGetSymbolAddress((void**)&qkv,  g_qkv);
    cudaGetSymbolAddress((void**)&attn, g_attn);
    cudaGetSymbolAddress((void**)&ff,   g_ff);

    embed_kernel<<<MTOK, 256>>>(tokens, embed_table, x);

    for (int l = 0; l < LL; l++) {
        rmsnorm_kernel<<<MTOK, 256>>>(x, g1 + (size_t)l * CC, h);
        sgemm_kernel<<<dim3(3*CC/128, MTOK/128), 256>>>(
            h, w_attn + (size_t)l * CC * 3 * CC, b_attn + (size_t)l * 3 * CC,
            nullptr, qkv, MTOK, 3*CC, CC, 0);
        rope_kernel<<<dim3(MTOK, 8), 128>>>(qkv);
        attention_kernel<<<dim3(TT/64, HH, BB), 64>>>(qkv, attn);
        sgemm_kernel<<<dim3(CC/128, MTOK/128), 256>>>(
            attn, w_proj + (size_t)l * CC * CC, b_proj + (size_t)l * CC,
            x, x, MTOK, CC, CC, 2);
        rmsnorm_kernel<<<MTOK, 256>>>(x, g2 + (size_t)l * CC, h);
        sgemm_kernel<<<dim3(PP*CC/128, MTOK/128), 256>>>(
            h, w_ff1 + (size_t)l * CC * PP * CC, b_ff1 + (size_t)l * PP * CC,
            nullptr, ff, MTOK, PP*CC, CC, 1);
        sgemm_kernel<<<dim3(CC/128, MTOK/128), 256>>>(
            ff, w_ff2 + (size_t)l * PP * CC * CC, b_ff2 + (size_t)l * CC,
            x, x, MTOK, CC, PP*CC, 2);
    }

    sgemm_kernel<<<dim3(VV/128, MTOK/128), 256>>>(
        x, w_out, nullptr, nullptr, out, MTOK, VV, CC, 0);
}

// round 3
// speedup vs baseline: 2.2191x; 2.2191x over previous
#include <cuda_runtime.h>
#include <cuda_bf16.h>
#include <math.h>
#include <stdint.h>

// ---------------- problem constants ----------------
#define BB 2
#define TT 1024
#define CC 1024
#define HH 16
#define HD 64
#define LL 6
#define PP 4
#define VV 32000
#define MTOK (BB*TT)          // 2048 rows

// ---------------- scratch (no allocation allowed) ----------------
__device__ float g_x   [MTOK * CC];
__device__ float g_h   [MTOK * CC];
__device__ float g_qkv [MTOK * 3 * CC];
__device__ float g_attn[MTOK * CC];
__device__ float g_ff  [MTOK * PP * CC];
__device__ double g_theta[512];

// transposed+split weights W^T [N][K] (K-major), bf16 hi/lo
#define WT_ATTN 0u
#define WT_PROJ (WT_ATTN + 6u*3072u*1024u)
#define WT_FF1  (WT_PROJ + 6u*1024u*1024u)
#define WT_FF2  (WT_FF1  + 6u*4096u*1024u)
#define WT_OUT  (WT_FF2  + 6u*1024u*4096u)
#define WT_TOTAL (WT_OUT + 32000u*1024u)
__device__ __nv_bfloat16 g_whi[WT_TOTAL];
__device__ __nv_bfloat16 g_wlo[WT_TOTAL];

// ---------------- helpers ----------------
__device__ __forceinline__ uint32_t smem_u32(const void* p) {
    uint32_t a;
    asm("{ .reg .u64 t; cvta.to.shared.u64 t, %1; cvt.u32.u64 %0, t; }"
        : "=r"(a) : "l"(p));
    return a;
}
__device__ __forceinline__ void cp_async16(uint32_t dst, const void* src) {
    asm volatile("cp.async.cg.shared.global [%0], [%1], 16;"
                 :: "r"(dst), "l"(__cvta_generic_to_global(src)) : "memory");
}
__device__ __forceinline__ void mma16816(float* c,
    uint32_t a0, uint32_t a1, uint32_t a2, uint32_t a3,
    uint32_t b0, uint32_t b1)
{
    asm volatile(
        "mma.sync.aligned.m16n8k16.row.col.f32.bf16.bf16.f32 "
        "{%0,%1,%2,%3},{%4,%5,%6,%7},{%8,%9},{%0,%1,%2,%3};"
        : "+f"(c[0]), "+f"(c[1]), "+f"(c[2]), "+f"(c[3])
        : "r"(a0), "r"(a1), "r"(a2), "r"(a3), "r"(b0), "r"(b1));
}
// 8 floats -> hi uint4 (8 bf16) + lo uint4 (8 bf16), round-to-nearest split
__device__ __forceinline__ void split8(float4 v0, float4 v1, uint4& hi, uint4& lo)
{
    float f[8] = {v0.x, v0.y, v0.z, v0.w, v1.x, v1.y, v1.z, v1.w};
    uint32_t h[4], l[4];
    #pragma unroll
    for (int e = 0; e < 4; e++) {
        __nv_bfloat162 hb = __floats2bfloat162_rn(f[2*e], f[2*e+1]);
        float r0 = f[2*e]   - __bfloat162float(hb.x);
        float r1 = f[2*e+1] - __bfloat162float(hb.y);
        __nv_bfloat162 lb = __floats2bfloat162_rn(r0, r1);
        h[e] = *reinterpret_cast<uint32_t*>(&hb);
        l[e] = *reinterpret_cast<uint32_t*>(&lb);
    }
    hi = make_uint4(h[0], h[1], h[2], h[3]);
    lo = make_uint4(l[0], l[1], l[2], l[3]);
}

// ---------------- embedding gather ----------------
__global__ void embed_kernel(const int* __restrict__ tokens,
                             const float* __restrict__ table,
                             float* __restrict__ x)
{
    int row = blockIdx.x;
    int tok = tokens[row];
    const float4* src = (const float4*)(table + (size_t)tok * CC);
    float4* dst = (float4*)(x + (size_t)row * CC);
    dst[threadIdx.x] = src[threadIdx.x];
}

__global__ void theta_init_kernel()
{
    int i = threadIdx.x;
    if (i < 512) g_theta[i] = exp(-(double)i * (9.210340371976184 / 512.0));
}

// ---------------- rmsnorm ----------------
__global__ void rmsnorm_kernel(const float* __restrict__ x,
                               const float* __restrict__ g,
                               float* __restrict__ h)
{
    int row = blockIdx.x;
    int tid = threadIdx.x;
    const float* xr = x + (size_t)row * CC;
    float ss = 0.f;
    #pragma unroll
    for (int i = tid; i < CC; i += 256) { float v = xr[i]; ss += v * v; }
    for (int o = 16; o > 0; o >>= 1) ss += __shfl_down_sync(0xffffffffu, ss, o);
    __shared__ float warp_s[8];
    __shared__ float sscale;
    int lane = tid & 31, wid = tid >> 5;
    if (lane == 0) warp_s[wid] = ss;
    __syncthreads();
    if (tid == 0) {
        float tot = 0.f;
        #pragma unroll
        for (int i = 0; i < 8; i++) tot += warp_s[i];
        sscale = rsqrtf(tot / (float)CC + 1.1920929e-07f);
    }
    __syncthreads();
    float s = sscale;
    float* hr = h + (size_t)row * CC;
    #pragma unroll
    for (int i = tid; i < CC; i += 256) hr[i] = xr[i] * s * g[i];
}

// ---------------- RoPE ----------------
__global__ void rope_kernel(float* __restrict__ qkv)
{
    int row = blockIdx.x;
    int t = row & (TT - 1);
    int p = blockIdx.y * 128 + threadIdx.x;
    int region = (p < 512) ? 0 : 1;
    int i = p - region * 512;
    double ang = (double)t * g_theta[i];
    double k = floor(ang * 0.15915494309189535);
    float a = (float)(ang - k * 6.283185307179586);
    float s, c;
    sincosf(a, &s, &c);
    float* base = qkv + (size_t)row * (3 * CC) + region * CC + 2 * i;
    float x0 = base[0], x1 = base[1];
    base[0] = x0 * c - x1 * s;
    base[1] = x1 * c + x0 * s;
}

// ---------------- flash attention (fp32) ----------------
__global__ void attention_kernel(const float* __restrict__ qkv,
                                 float* __restrict__ out)
{
    __shared__ float Ks[32][64];
    __shared__ float Vs[32][64];
    __shared__ float Ps[32][64];
    int mt = blockIdx.x, h = blockIdx.y, b = blockIdx.z;
    int tid = threadIdx.x;
    int qrow = mt * 64 + tid;

    const float* qp = qkv + ((size_t)(b * TT + qrow) * (3 * CC)) + h * HD;
    float q[64];
    #pragma unroll
    for (int u = 0; u < 16; u++) {
        float4 v = *(const float4*)(qp + 4 * u);
        q[4*u+0] = v.x; q[4*u+1] = v.y; q[4*u+2] = v.z; q[4*u+3] = v.w;
    }
    float acc[64];
    #pragma unroll
    for (int u = 0; u < 64; u++) acc[u] = 0.f;
    float mrun = -1e30f, lsum = 0.f;

    int jmax = 2 * mt + 1;
    int krow = tid >> 1;
    int seg  = (tid & 1) * 32;
    for (int j = 0; j <= jmax; j++) {
        const float* kp = qkv + ((size_t)(b * TT + j * 32 + krow) * (3 * CC)) + CC + h * HD + seg;
        const float* vp = kp + CC;
        #pragma unroll
        for (int u = 0; u < 8; u++) {
            *(float4*)&Ks[krow][seg + 4*u] = *(const float4*)(kp + 4*u);
            *(float4*)&Vs[krow][seg + 4*u] = *(const float4*)(vp + 4*u);
        }
        __syncthreads();

        float tmax = -1e30f;
        #pragma unroll 4
        for (int kk = 0; kk < 32; kk++) {
            int kt = j * 32 + kk;
            float s = -1e30f;
            if (kt <= qrow) {
                float d = 0.f;
                #pragma unroll
                for (int u = 0; u < 64; u++) d += q[u] * Ks[kk][u];
                s = d * 0.125f;
            }
            Ps[kk][tid] = s;
            tmax = fmaxf(tmax, s);
        }
        float mnew = fmaxf(mrun, tmax);
        float corr = expf(mrun - mnew);
        lsum *= corr;
        #pragma unroll
        for (int u = 0; u < 64; u++) acc[u] *= corr;
        #pragma unroll 2
        for (int kk = 0; kk < 32; kk++) {
            float pexp = expf(Ps[kk][tid] - mnew);
            lsum += pexp;
            #pragma unroll
            for (int u = 0; u < 64; u++) acc[u] += pexp * Vs[kk][u];
        }
        mrun = mnew;
        __syncthreads();
    }
    float inv = 1.0f / lsum;
    float* op = out + ((size_t)(b * TT + qrow) * CC) + h * HD;
    #pragma unroll
    for (int u = 0; u < 64; u++) op[u] = acc[u] * inv;
}

// ---------------- weight transpose + split: src[R][Cn] f32 -> hi/lo[Cn][R] bf16 ----------------
__global__ void transpose_split_kernel(const float* __restrict__ src,
                                       __nv_bfloat16* __restrict__ hi,
                                       __nv_bfloat16* __restrict__ lo,
                                       int R, int Cn)
{
    __shared__ float t[32][33];
    int bx = blockIdx.x * 32;   // Cn dir
    int by = blockIdx.y * 32;   // R dir
    int tx = threadIdx.x, ty = threadIdx.y;
    #pragma unroll
    for (int i = 0; i < 32; i += 8)
        t[ty + i][tx] = src[(size_t)(by + ty + i) * Cn + bx + tx];
    __syncthreads();
    #pragma unroll
    for (int i = 0; i < 32; i += 8) {
        float v = t[tx][ty + i];
        __nv_bfloat16 hb = __float2bfloat16_rn(v);
        float r = v - __bfloat162float(hb);
        size_t idx = (size_t)(bx + ty + i) * R + by + tx;
        hi[idx] = hb;
        lo[idx] = __float2bfloat16_rn(r);
    }
}

// ---------------- split-bf16 HMMA GEMM ----------------
// C[M,N] = A[M,K](f32) @ W[N,K]^T (split bf16 hi/lo), 3-pass (hh + hl + lh)
// 128x128 block, BK=32, 3-stage pipeline, 8 warps (4M x 2N), 32x64 warp tile
// mode: 0 = bias, 1 = bias+gelu, 2 = bias+residual
#define LDK 40              // 32 + 8 pad (elements)
#define TILE_B (128*LDK*2)  // 10240 bytes per matrix
#define STAGE_B (4*TILE_B)  // Ah, Al, Bh, Bl
#define GSMEM_BYTES (3*STAGE_B)  // 122880

__global__ __launch_bounds__(256)
void gemm_mma(const float* __restrict__ A,
              const __nv_bfloat16* __restrict__ Whi,
              const __nv_bfloat16* __restrict__ Wlo,
              const float* __restrict__ bias, const float* __restrict__ res,
              float* __restrict__ C, int M, int N, int K, int mode)
{
    extern __shared__ char dsm[];
    uint32_t sb = smem_u32(dsm);

    int tid = threadIdx.x;
    int w = tid >> 5, lane = tid & 31;
    int wm = w & 3, wn = w >> 2;
    int lr = lane >> 2, lc2 = (lane & 3) * 2;   // frag row / k-pair
    int bn = blockIdx.x * 128, bm = blockIdx.y * 128;

    // loader mapping
    int arow = tid >> 1;            // 0..127
    int kseg = (tid & 1) * 16;      // elems 0 or 16

    float c[2][8][4];
    #pragma unroll
    for (int i = 0; i < 2; i++)
        #pragma unroll
        for (int j = 0; j < 8; j++)
            #pragma unroll
            for (int e = 0; e < 4; e++) c[i][j][e] = 0.f;

    const float* Ap = A + (size_t)(bm + arow) * K + kseg;
    const __nv_bfloat16* Bhp = Whi + (size_t)(bn + arow) * K + kseg;
    const __nv_bfloat16* Blp = Wlo + (size_t)(bn + arow) * K + kseg;
    uint32_t a_st = sb + arow * (LDK*2) + kseg * 2;               // byte addr in Ah
    uint32_t b_st = sb + 2*TILE_B + arow * (LDK*2) + kseg * 2;    // byte addr in Bh

    int NT = K / 32;

    // prologue: stages 0,1
    #pragma unroll
    for (int s = 0; s < 2; s++) {
        uint32_t stg = (uint32_t)s * STAGE_B;
        cp_async16(b_st + stg,          Bhp + s*32);
        cp_async16(b_st + stg + 16,     Bhp + s*32 + 8);
        cp_async16(b_st + stg + TILE_B,      Blp + s*32);
        cp_async16(b_st + stg + TILE_B + 16, Blp + s*32 + 8);
        asm volatile("cp.async.commit_group;" ::: "memory");
        const float4* ap = (const float4*)(Ap + s*32);
        float4 v0 = ap[0], v1 = ap[1], v2 = ap[2], v3 = ap[3];
        uint4 h0, l0, h1, l1;
        split8(v0, v1, h0, l0);
        split8(v2, v3, h1, l1);
        *(uint4*)(dsm + (a_st - sb) + s*STAGE_B)               = h0;
        *(uint4*)(dsm + (a_st - sb) + s*STAGE_B + 16)          = h1;
        *(uint4*)(dsm + (a_st - sb) + s*STAGE_B + TILE_B)      = l0;
        *(uint4*)(dsm + (a_st - sb) + s*STAGE_B + TILE_B + 16) = l1;
    }

    int buf = 0;
    for (int j = 0; j < NT; j++) {
        asm volatile("cp.async.wait_group 1;" ::: "memory");
        __syncthreads();

        int jp = j + 2;
        int pbuf = buf + 2; if (pbuf >= 3) pbuf -= 3;
        float4 pv0, pv1, pv2, pv3;
        bool pre = (jp < NT);
        if (pre) {
            uint32_t stg = (uint32_t)pbuf * STAGE_B;
            cp_async16(b_st + stg,          Bhp + jp*32);
            cp_async16(b_st + stg + 16,     Bhp + jp*32 + 8);
            cp_async16(b_st + stg + TILE_B,      Blp + jp*32);
            cp_async16(b_st + stg + TILE_B + 16, Blp + jp*32 + 8);
            const float4* ap = (const float4*)(Ap + jp*32);
            pv0 = ap[0]; pv1 = ap[1]; pv2 = ap[2]; pv3 = ap[3];
        }
        asm volatile("cp.async.commit_group;" ::: "memory");

        // compute from buf
        const char* s = dsm + buf * STAGE_B;
        const char* sAh = s;
        const char* sAl = s + TILE_B;
        const char* sBh = s + 2*TILE_B;
        const char* sBl = s + 3*TILE_B;
        #pragma unroll
        for (int ko = 0; ko < 32; ko += 16) {
            uint32_t ah[2][4], al[2][4];
            #pragma unroll
            for (int mt = 0; mt < 2; mt++) {
                int row = wm*32 + mt*16 + lr;
                const char* p = sAh + row*(LDK*2) + (ko + lc2)*2;
                ah[mt][0] = *(const uint32_t*)p;
                ah[mt][1] = *(const uint32_t*)(p + 8*(LDK*2));
                ah[mt][2] = *(const uint32_t*)(p + 16);
                ah[mt][3] = *(const uint32_t*)(p + 8*(LDK*2) + 16);
                const char* q = sAl + row*(LDK*2) + (ko + lc2)*2;
                al[mt][0] = *(const uint32_t*)q;
                al[mt][1] = *(const uint32_t*)(q + 8*(LDK*2));
                al[mt][2] = *(const uint32_t*)(q + 16);
                al[mt][3] = *(const uint32_t*)(q + 8*(LDK*2) + 16);
            }
            uint32_t bh[8][2], bl[8][2];
            #pragma unroll
            for (int nt = 0; nt < 8; nt++) {
                int n = wn*64 + nt*8 + lr;
                const char* p = sBh + n*(LDK*2) + (ko + lc2)*2;
                bh[nt][0] = *(const uint32_t*)p;
                bh[nt][1] = *(const uint32_t*)(p + 16);
                const char* q = sBl + n*(LDK*2) + (ko + lc2)*2;
                bl[nt][0] = *(const uint32_t*)q;
                bl[nt][1] = *(const uint32_t*)(q + 16);
            }
            #pragma unroll
            for (int mt = 0; mt < 2; mt++)
                #pragma unroll
                for (int nt = 0; nt < 8; nt++) {
                    mma16816(c[mt][nt], ah[mt][0], ah[mt][1], ah[mt][2], ah[mt][3],
                             bh[nt][0], bh[nt][1]);
                    mma16816(c[mt][nt], ah[mt][0], ah[mt][1], ah[mt][2], ah[mt][3],
                             bl[nt][0], bl[nt][1]);
                    mma16816(c[mt][nt], al[mt][0], al[mt][1], al[mt][2], al[mt][3],
                             bh[nt][0], bh[nt][1]);
                }
        }

        if (pre) {
            uint4 h0, l0, h1, l1;
            split8(pv0, pv1, h0, l0);
            split8(pv2, pv3, h1, l1);
            char* d = dsm + (a_st - sb) + pbuf*STAGE_B;
            *(uint4*)(d)               = h0;
            *(uint4*)(d + 16)          = h1;
            *(uint4*)(d + TILE_B)      = l0;
            *(uint4*)(d + TILE_B + 16) = l1;
        }
        buf++; if (buf >= 3) buf = 0;
    }

    // epilogue
    #pragma unroll
    for (int mt = 0; mt < 2; mt++) {
        #pragma unroll
        for (int nt = 0; nt < 8; nt++) {
            int col = bn + wn*64 + nt*8 + lc2;
            float bx_ = 0.f, by_ = 0.f;
            if (bias) { bx_ = bias[col]; by_ = bias[col+1]; }
            #pragma unroll
            for (int half = 0; half < 2; half++) {
                int row = bm + wm*32 + mt*16 + lr + half*8;
                float v0 = c[mt][nt][half*2+0] + bx_;
                float v1 = c[mt][nt][half*2+1] + by_;
                if (mode == 1) {
                    v0 = 0.5f * v0 * (1.0f + erff(v0 * 0.70710678118654752f));
                    v1 = 0.5f * v1 * (1.0f + erff(v1 * 0.70710678118654752f));
                } else if (mode == 2) {
                    float2 rv = *(const float2*)(res + (size_t)row * N + col);
                    v0 += rv.x; v1 += rv.y;
                }
                *(float2*)(C + (size_t)row * N + col) = make_float2(v0, v1);
            }
        }
    }
}

// ---------------- launch ----------------
extern "C" void kernel_launch(void* const* d_in, const int* in_sizes, int n_in,
                              void* d_out, int out_size)
{
    const int*   tokens      = (const int*)  d_in[0];
    const float* embed_table = (const float*)d_in[1];
    const float* w_attn      = (const float*)d_in[2];
    const float* b_attn      = (const float*)d_in[3];
    const float* w_proj      = (const float*)d_in[4];
    const float* b_proj      = (const float*)d_in[5];
    const float* g1          = (const float*)d_in[6];
    const float* g2          = (const float*)d_in[7];
    const float* w_ff1       = (const float*)d_in[8];
    const float* b_ff1       = (const float*)d_in[9];
    const float* w_ff2       = (const float*)d_in[10];
    const float* b_ff2       = (const float*)d_in[11];
    const float* w_out       = (const float*)d_in[12];
    float* out = (float*)d_out;

    float *x, *h, *qkv, *attn, *ff;
    __nv_bfloat16 *whi, *wlo;
    cudaGetSymbolAddress((void**)&x,    g_x);
    cudaGetSymbolAddress((void**)&h,    g_h);
    cudaGetSymbolAddress((void**)&qkv,  g_qkv);
    cudaGetSymbolAddress((void**)&attn, g_attn);
    cudaGetSymbolAddress((void**)&ff,   g_ff);
    cudaGetSymbolAddress((void**)&whi,  g_whi);
    cudaGetSymbolAddress((void**)&wlo,  g_wlo);

    static int smem_set = 0;
    if (!smem_set) {
        cudaFuncSetAttribute(gemm_mma, cudaFuncAttributeMaxDynamicSharedMemorySize, GSMEM_BYTES);
        smem_set = 1;
    }

    // weight transpose + split (per replay)
    dim3 tb(32, 8);
    for (int l = 0; l < LL; l++) {
        transpose_split_kernel<<<dim3(3*CC/32, CC/32), tb>>>(
            w_attn + (size_t)l*CC*3*CC, whi + WT_ATTN + (size_t)l*3*CC*CC,
            wlo + WT_ATTN + (size_t)l*3*CC*CC, CC, 3*CC);
        transpose_split_kernel<<<dim3(CC/32, CC/32), tb>>>(
            w_proj + (size_t)l*CC*CC, whi + WT_PROJ + (size_t)l*CC*CC,
            wlo + WT_PROJ + (size_t)l*CC*CC, CC, CC);
        transpose_split_kernel<<<dim3(PP*CC/32, CC/32), tb>>>(
            w_ff1 + (size_t)l*CC*PP*CC, whi + WT_FF1 + (size_t)l*PP*CC*CC,
            wlo + WT_FF1 + (size_t)l*PP*CC*CC, CC, PP*CC);
        transpose_split_kernel<<<dim3(CC/32, PP*CC/32), tb>>>(
            w_ff2 + (size_t)l*PP*CC*CC, whi + WT_FF2 + (size_t)l*CC*PP*CC,
            wlo + WT_FF2 + (size_t)l*CC*PP*CC, PP*CC, CC);
    }
    transpose_split_kernel<<<dim3(VV/32, CC/32), tb>>>(
        w_out, whi + WT_OUT, wlo + WT_OUT, CC, VV);

    theta_init_kernel<<<1, 512>>>();
    embed_kernel<<<MTOK, 256>>>(tokens, embed_table, x);

    for (int l = 0; l < LL; l++) {
        rmsnorm_kernel<<<MTOK, 256>>>(x, g1 + (size_t)l * CC, h);
        gemm_mma<<<dim3(3*CC/128, MTOK/128), 256, GSMEM_BYTES>>>(
            h, whi + WT_ATTN + (size_t)l*3*CC*CC, wlo + WT_ATTN + (size_t)l*3*CC*CC,
            b_attn + (size_t)l*3*CC, nullptr, qkv, MTOK, 3*CC, CC, 0);
        rope_kernel<<<dim3(MTOK, 8), 128>>>(qkv);
        attention_kernel<<<dim3(TT/64, HH, BB), 64>>>(qkv, attn);
        gemm_mma<<<dim3(CC/128, MTOK/128), 256, GSMEM_BYTES>>>(
            attn, whi + WT_PROJ + (size_t)l*CC*CC, wlo + WT_PROJ + (size_t)l*CC*CC,
            b_proj + (size_t)l*CC, x, x, MTOK, CC, CC, 2);
        rmsnorm_kernel<<<MTOK, 256>>>(x, g2 + (size_t)l * CC, h);
        gemm_mma<<<dim3(PP*CC/128, MTOK/128), 256, GSMEM_BYTES>>>(
            h, whi + WT_FF1 + (size_t)l*PP*CC*CC, wlo + WT_FF1 + (size_t)l*PP*CC*CC,
            b_ff1 + (size_t)l*PP*CC, nullptr, ff, MTOK, PP*CC, CC, 1);
        gemm_mma<<<dim3(CC/128, MTOK/128), 256, GSMEM_BYTES>>>(
            ff, whi + WT_FF2 + (size_t)l*CC*PP*CC, wlo + WT_FF2 + (size_t)l*CC*PP*CC,
            b_ff2 + (size_t)l*CC, x, x, MTOK, CC, PP*CC, 2);
    }

    gemm_mma<<<dim3(VV/128, MTOK/128), 256, GSMEM_BYTES>>>(
        x, whi + WT_OUT, wlo + WT_OUT, nullptr, nullptr, out, MTOK, VV, CC, 0);
}